// round 2
// baseline (speedup 1.0000x reference)
#include <cuda_runtime.h>
#include <math.h>

// Problem constants (fixed per this problem instance)
#define NNODES 32768          // B*IDX = 256*128
#define NEDGES 262144
#define NB     256            // batches
#define IDXN   128            // nodes per batch
#define ND     128            // ndim
#define J1     1408           // U(256) R(256) Vf(256) Vr(256) gh(384)
#define J2     384            // gi width
#define J3     320            // padded 258 -> 320 (fm 128 | gm 1 | fm2 128 | gm2 1 | pad)

// ---------------- persistent device scratch (no allocations allowed) ----------------
__device__ float g_hf[(size_t)NNODES * ND];
__device__ float g_M1[(size_t)NNODES * J1];     // 184 MB
__device__ float g_agg[(size_t)NNODES * 256];
__device__ float g_gi[(size_t)NNODES * J2];
__device__ float g_S[(size_t)NNODES * J3];
__device__ float g_W1[2 * 128 * J1];
__device__ float g_b1[2 * J1];
__device__ float g_W2[2 * 256 * J2];
__device__ float g_b2[2 * J2];
__device__ float g_W3[128 * J3];
__device__ float g_b3[J3];
__device__ int g_cnt_in[NNODES], g_cnt_out[NNODES];
__device__ int g_cur_in[NNODES], g_cur_out[NNODES];
__device__ int g_row_in[NNODES + 1], g_row_out[NNODES + 1];
__device__ int g_cin[NEDGES], g_cout[NEDGES];

// ---------------- small utility kernels ----------------
__global__ void copy_h_kernel(const float* __restrict__ h) {
    int i = blockIdx.x * blockDim.x + threadIdx.x;
    g_hf[i] = h[i];
}

// Pack W1: [l][k][j], k<128, j<1408
// j in [0,256): A_f = msg_W[l][j][k]        (acts on h_j of fwd edges)
// j in [256,512): A_r = msgr_W[l][j-256][k]
// j in [512,768): B_f = msg_W[l][j-512][128+k]
// j in [768,1024): B_r = msgr_W[l][j-768][128+k]
// j in [1024,1408): Whh = gru_Whh[l][j-1024][k]
__global__ void pack_w1_kernel(const float* __restrict__ msgW,
                               const float* __restrict__ msgrW,
                               const float* __restrict__ Whh) {
    int idx = blockIdx.x * blockDim.x + threadIdx.x;
    if (idx >= 2 * 128 * J1) return;
    int l = idx / (128 * J1);
    int rem = idx % (128 * J1);
    int k = rem / J1;
    int j = rem % J1;
    float v;
    if (j < 256)        v = msgW [l * 65536 + j * 256 + k];
    else if (j < 512)   v = msgrW[l * 65536 + (j - 256) * 256 + k];
    else if (j < 768)   v = msgW [l * 65536 + (j - 512) * 256 + 128 + k];
    else if (j < 1024)  v = msgrW[l * 65536 + (j - 768) * 256 + 128 + k];
    else                v = Whh  [l * 49152 + (j - 1024) * 128 + k];
    g_W1[idx] = v;
}

__global__ void pack_b1_kernel(const float* __restrict__ msgb,
                               const float* __restrict__ msgrb,
                               const float* __restrict__ bhh) {
    int idx = blockIdx.x * blockDim.x + threadIdx.x;
    if (idx >= 2 * J1) return;
    int l = idx / J1;
    int j = idx % J1;
    float v = 0.f;
    if (j >= 512 && j < 768)        v = msgb [l * 256 + (j - 512)];
    else if (j >= 768 && j < 1024)  v = msgrb[l * 256 + (j - 768)];
    else if (j >= 1024)             v = bhh  [l * 384 + (j - 1024)];
    g_b1[idx] = v;
}

__global__ void pack_w2_kernel(const float* __restrict__ Wih) {
    int idx = blockIdx.x * blockDim.x + threadIdx.x;
    if (idx >= 2 * 256 * J2) return;
    int l = idx / (256 * J2);
    int rem = idx % (256 * J2);
    int k = rem / J2;
    int j = rem % J2;
    g_W2[idx] = Wih[l * 98304 + j * 256 + k];
}

__global__ void pack_b2_kernel(const float* __restrict__ bih) {
    int idx = blockIdx.x * blockDim.x + threadIdx.x;
    if (idx >= 2 * J2) return;
    g_b2[idx] = bih[idx];   // same [l][j] layout
}

__global__ void pack_w3_kernel(const float* __restrict__ fmW, const float* __restrict__ gmW,
                               const float* __restrict__ fm2W, const float* __restrict__ gm2W) {
    int idx = blockIdx.x * blockDim.x + threadIdx.x;
    if (idx >= 128 * J3) return;
    int k = idx / J3;
    int j = idx % J3;
    float v = 0.f;
    if (j < 128)            v = fmW [j * 128 + k];
    else if (j == 128)      v = gmW [k];
    else if (j < 257)       v = fm2W[(j - 129) * 128 + k];
    else if (j == 257)      v = gm2W[k];
    g_W3[idx] = v;
}

__global__ void pack_b3_kernel(const float* __restrict__ fmb, const float* __restrict__ gmb,
                               const float* __restrict__ fm2b, const float* __restrict__ gm2b) {
    int j = blockIdx.x * blockDim.x + threadIdx.x;
    if (j >= J3) return;
    float v = 0.f;
    if (j < 128)            v = fmb[j];
    else if (j == 128)      v = gmb[0];
    else if (j < 257)       v = fm2b[j - 129];
    else if (j == 257)      v = gm2b[0];
    g_b3[j] = v;
}

// ---------------- CSR build ----------------
__global__ void zero_csr_kernel() {
    int i = blockIdx.x * blockDim.x + threadIdx.x;
    if (i < NNODES) {
        g_cnt_in[i] = 0; g_cnt_out[i] = 0;
        g_cur_in[i] = 0; g_cur_out[i] = 0;
    }
}

__global__ void hist_kernel(const int* __restrict__ ei) {
    int e = blockIdx.x * blockDim.x + threadIdx.x;
    if (e >= NEDGES) return;
    int s = ei[e];
    int t = ei[NEDGES + e];
    atomicAdd(&g_cnt_in[t], 1);    // fwd edge lands at t
    atomicAdd(&g_cnt_out[s], 1);   // rev edge lands at s
}

// single-block exclusive scan (1024 threads x 32 values) for both arrays
__global__ void scan_kernel() {
    __shared__ int sums[1024];
    int t = threadIdx.x;
    for (int a = 0; a < 2; a++) {
        const int* cnt = a ? g_cnt_out : g_cnt_in;
        int* row = a ? g_row_out : g_row_in;
        int base = t * 32;
        int vals[32];
        int local = 0;
        #pragma unroll
        for (int i = 0; i < 32; i++) { vals[i] = cnt[base + i]; local += vals[i]; }
        sums[t] = local;
        __syncthreads();
        // inclusive Hillis-Steele scan over 1024 partials
        for (int off = 1; off < 1024; off <<= 1) {
            int v = (t >= off) ? sums[t - off] : 0;
            __syncthreads();
            sums[t] += v;
            __syncthreads();
        }
        int run = sums[t] - local;   // exclusive offset for this thread's segment
        #pragma unroll
        for (int i = 0; i < 32; i++) { row[base + i] = run; run += vals[i]; }
        if (t == 1023) row[NNODES] = run;
        __syncthreads();
    }
}

__global__ void fill_kernel(const int* __restrict__ ei) {
    int e = blockIdx.x * blockDim.x + threadIdx.x;
    if (e >= NEDGES) return;
    int s = ei[e];
    int t = ei[NEDGES + e];
    int p = atomicAdd(&g_cur_in[t], 1);
    g_cin[g_row_in[t] + p] = s;          // in-list of t holds sources
    int q = atomicAdd(&g_cur_out[s], 1);
    g_cout[g_row_out[s] + q] = t;        // out-list of s holds targets
}

// ---------------- generic tiled fp32 GEMM: C[N,J] = X[N,K] @ W[K,J] + bias ----------------
// BM=128, BN=64, BK=16, 256 threads, 8x4 microtile. All dims divide evenly (no guards).
template <int K, int J>
__device__ __forceinline__ void gemm_core(const float* __restrict__ X,
                                          const float* __restrict__ W,
                                          const float* __restrict__ bias,
                                          float* __restrict__ C) {
    constexpr int BM = 128, BN = 64, BK = 16;
    __shared__ float Xs[BK][BM + 4];
    __shared__ float Ws[BK][BN];
    const int tid = threadIdx.x;
    const int bm = blockIdx.x * BM;
    const int bn = blockIdx.y * BN;
    const int tx = tid & 15;
    const int ty = tid >> 4;
    const int tm0 = ty * 8;
    const int tn0 = tx * 4;

    float acc[8][4];
    #pragma unroll
    for (int m = 0; m < 8; m++)
        #pragma unroll
        for (int n = 0; n < 4; n++) acc[m][n] = 0.f;

    const int xr0 = tid >> 2;             // 0..63
    const int xc  = (tid & 3) * 4;        // 0,4,8,12
    const int wr  = tid >> 4;             // 0..15
    const int wc  = (tid & 15) * 4;       // 0..60

    for (int k0 = 0; k0 < K; k0 += BK) {
        float4 a0 = *(const float4*)(X + (size_t)(bm + xr0) * K + k0 + xc);
        float4 a1 = *(const float4*)(X + (size_t)(bm + xr0 + 64) * K + k0 + xc);
        float4 b0 = *(const float4*)(W + (size_t)(k0 + wr) * J + bn + wc);
        Xs[xc + 0][xr0] = a0.x; Xs[xc + 1][xr0] = a0.y;
        Xs[xc + 2][xr0] = a0.z; Xs[xc + 3][xr0] = a0.w;
        Xs[xc + 0][xr0 + 64] = a1.x; Xs[xc + 1][xr0 + 64] = a1.y;
        Xs[xc + 2][xr0 + 64] = a1.z; Xs[xc + 3][xr0 + 64] = a1.w;
        *(float4*)&Ws[wr][wc] = b0;
        __syncthreads();
        #pragma unroll
        for (int kk = 0; kk < BK; kk++) {
            float4 xa = *(const float4*)&Xs[kk][tm0];
            float4 xb = *(const float4*)&Xs[kk][tm0 + 4];
            float4 wv = *(const float4*)&Ws[kk][tn0];
            float xr[8] = {xa.x, xa.y, xa.z, xa.w, xb.x, xb.y, xb.z, xb.w};
            float wg[4] = {wv.x, wv.y, wv.z, wv.w};
            #pragma unroll
            for (int m = 0; m < 8; m++)
                #pragma unroll
                for (int n = 0; n < 4; n++)
                    acc[m][n] += xr[m] * wg[n];
        }
        __syncthreads();
    }
    float b0 = bias[bn + tn0 + 0];
    float b1 = bias[bn + tn0 + 1];
    float b2 = bias[bn + tn0 + 2];
    float b3 = bias[bn + tn0 + 3];
    #pragma unroll
    for (int m = 0; m < 8; m++) {
        int r = bm + tm0 + m;
        float4 v;
        v.x = acc[m][0] + b0;
        v.y = acc[m][1] + b1;
        v.z = acc[m][2] + b2;
        v.w = acc[m][3] + b3;
        *(float4*)(C + (size_t)r * J + bn + tn0) = v;
    }
}

__global__ void __launch_bounds__(256) gemm1_kernel(int l) {
    gemm_core<128, J1>(g_hf, g_W1 + l * 128 * J1, g_b1 + l * J1, g_M1);
}
__global__ void __launch_bounds__(256) gemm2_kernel(int l) {
    gemm_core<256, J2>(g_agg, g_W2 + l * 256 * J2, g_b2 + l * J2, g_gi);
}
__global__ void __launch_bounds__(256) gemm3_kernel(const float* __restrict__ Xn) {
    gemm_core<128, J3>(Xn, g_W3, g_b3, g_S);
}

// ---------------- aggregation: agg[i] = sum_in U[src] + sum_out R[tgt] + din*Vf[i] + dout*Vr[i] ----------------
__global__ void __launch_bounds__(256) aggregate_kernel() {
    int n = blockIdx.x;
    int j = threadIdx.x;   // 0..255
    __shared__ int nb[256];
    float acc = 0.f;

    int beg = g_row_in[n], end = g_row_in[n + 1];
    float din = (float)(end - beg);
    for (int c = beg; c < end; c += 256) {
        int cnt = min(256, end - c);
        if (j < cnt) nb[j] = g_cin[c + j];
        __syncthreads();
        int p = 0;
        for (; p + 4 <= cnt; p += 4) {
            int n0 = nb[p], n1 = nb[p + 1], n2 = nb[p + 2], n3 = nb[p + 3];
            float v0 = g_M1[(size_t)n0 * J1 + j];
            float v1 = g_M1[(size_t)n1 * J1 + j];
            float v2 = g_M1[(size_t)n2 * J1 + j];
            float v3 = g_M1[(size_t)n3 * J1 + j];
            acc += (v0 + v1) + (v2 + v3);
        }
        for (; p < cnt; p++) acc += g_M1[(size_t)nb[p] * J1 + j];
        __syncthreads();
    }

    beg = g_row_out[n]; end = g_row_out[n + 1];
    float dout = (float)(end - beg);
    for (int c = beg; c < end; c += 256) {
        int cnt = min(256, end - c);
        if (j < cnt) nb[j] = g_cout[c + j];
        __syncthreads();
        int p = 0;
        for (; p + 4 <= cnt; p += 4) {
            int n0 = nb[p], n1 = nb[p + 1], n2 = nb[p + 2], n3 = nb[p + 3];
            float v0 = g_M1[(size_t)n0 * J1 + 256 + j];
            float v1 = g_M1[(size_t)n1 * J1 + 256 + j];
            float v2 = g_M1[(size_t)n2 * J1 + 256 + j];
            float v3 = g_M1[(size_t)n3 * J1 + 256 + j];
            acc += (v0 + v1) + (v2 + v3);
        }
        for (; p < cnt; p++) acc += g_M1[(size_t)nb[p] * J1 + 256 + j];
        __syncthreads();
    }

    const float* own = g_M1 + (size_t)n * J1;
    acc += din * own[512 + j] + dout * own[768 + j];
    g_agg[(size_t)n * 256 + j] = acc;
}

// ---------------- GRU elementwise update (in place on g_hf) ----------------
__global__ void gru_kernel() {
    int idx = blockIdx.x * blockDim.x + threadIdx.x;   // N*128
    int n = idx >> 7;
    int d = idx & 127;
    const float* gi = g_gi + (size_t)n * J2;
    const float* gh = g_M1 + (size_t)n * J1 + 1024;
    float r = 1.f / (1.f + expf(-(gi[d] + gh[d])));
    float z = 1.f / (1.f + expf(-(gi[128 + d] + gh[128 + d])));
    float nn = tanhf(gi[256 + d] + r * gh[256 + d]);
    float h = g_hf[idx];
    g_hf[idx] = (1.f - z) * nn + z * h;
}

// ---------------- row-normalize hf -> output ----------------
__global__ void normalize_kernel(float* __restrict__ out) {
    int n = blockIdx.x;
    int d = threadIdx.x;   // 128
    float v = g_hf[(size_t)n * 128 + d];
    __shared__ float red[128];
    red[d] = v * v;
    __syncthreads();
    for (int s = 64; s > 0; s >>= 1) {
        if (d < s) red[d] += red[d + s];
        __syncthreads();
    }
    float norm = sqrtf(red[0]);
    out[(size_t)n * 128 + d] = v / fmaxf(norm, 1e-12f);
}

// ---------------- gated segment-sum readouts, per batch ----------------
__global__ void batch_reduce_kernel(float* __restrict__ outG, float* __restrict__ outG2) {
    int b = blockIdx.x;
    int d = threadIdx.x;   // 128
    __shared__ float g1s[IDXN], g2s[IDXN];
    const float* S = g_S + (size_t)b * IDXN * J3;
    g1s[d] = 1.f / (1.f + expf(-S[(size_t)d * J3 + 128]));
    g2s[d] = 1.f / (1.f + expf(-S[(size_t)d * J3 + 257]));
    __syncthreads();
    float a1 = 0.f, a2 = 0.f;
    for (int i = 0; i < IDXN; i++) {
        const float* row = S + (size_t)i * J3;
        a1 += row[d] * g1s[i];
        a2 += row[129 + d] * g2s[i];
    }
    __shared__ float red[128];
    red[d] = a1 * a1;
    __syncthreads();
    for (int s = 64; s > 0; s >>= 1) { if (d < s) red[d] += red[d + s]; __syncthreads(); }
    float n1 = sqrtf(red[0]);
    __syncthreads();
    red[d] = a2 * a2;
    __syncthreads();
    for (int s = 64; s > 0; s >>= 1) { if (d < s) red[d] += red[d + s]; __syncthreads(); }
    float n2 = sqrtf(red[0]);
    outG [b * 128 + d] = a1 / fmaxf(n1, 1e-12f);
    outG2[b * 128 + d] = a2 / fmaxf(n2, 1e-12f);
}

// ---------------- launch ----------------
extern "C" void kernel_launch(void* const* d_in, const int* in_sizes, int n_in,
                              void* d_out, int out_size) {
    const float* h     = (const float*)d_in[0];
    const int*   ei    = (const int*)  d_in[1];
    const float* msgW  = (const float*)d_in[2];
    const float* msgb  = (const float*)d_in[3];
    const float* msgrW = (const float*)d_in[4];
    const float* msgrb = (const float*)d_in[5];
    const float* Wih   = (const float*)d_in[6];
    const float* Whh   = (const float*)d_in[7];
    const float* bih   = (const float*)d_in[8];
    const float* bhh   = (const float*)d_in[9];
    const float* fmW   = (const float*)d_in[10];
    const float* fmb   = (const float*)d_in[11];
    const float* gmW   = (const float*)d_in[12];
    const float* gmb   = (const float*)d_in[13];
    const float* fm2W  = (const float*)d_in[14];
    const float* fm2b  = (const float*)d_in[15];
    const float* gm2W  = (const float*)d_in[16];
    const float* gm2b  = (const float*)d_in[17];

    float* out    = (float*)d_out;
    float* out_hf = out;
    float* out_G  = out + (size_t)NNODES * ND;
    float* out_G2 = out_G + NB * ND;

    copy_h_kernel<<<(NNODES * ND) / 256, 256>>>(h);
    pack_w1_kernel<<<(2 * 128 * J1 + 255) / 256, 256>>>(msgW, msgrW, Whh);
    pack_b1_kernel<<<(2 * J1 + 255) / 256, 256>>>(msgb, msgrb, bhh);
    pack_w2_kernel<<<(2 * 256 * J2 + 255) / 256, 256>>>(Wih);
    pack_b2_kernel<<<(2 * J2 + 255) / 256, 256>>>(bih);
    pack_w3_kernel<<<(128 * J3 + 255) / 256, 256>>>(fmW, gmW, fm2W, gm2W);
    pack_b3_kernel<<<(J3 + 255) / 256, 256>>>(fmb, gmb, fm2b, gm2b);

    zero_csr_kernel<<<(NNODES + 255) / 256, 256>>>();
    hist_kernel<<<(NEDGES + 255) / 256, 256>>>(ei);
    scan_kernel<<<1, 1024>>>();
    fill_kernel<<<(NEDGES + 255) / 256, 256>>>(ei);

    for (int l = 0; l < 2; l++) {
        gemm1_kernel<<<dim3(NNODES / 128, J1 / 64), 256>>>(l);
        aggregate_kernel<<<NNODES, 256>>>();
        gemm2_kernel<<<dim3(NNODES / 128, J2 / 64), 256>>>(l);
        gru_kernel<<<(NNODES * ND) / 256, 256>>>();
    }

    normalize_kernel<<<NNODES, 128>>>(out_hf);
    gemm3_kernel<<<dim3(NNODES / 128, J3 / 64), 256>>>(out_hf);
    batch_reduce_kernel<<<NB, 128>>>(out_G, out_G2);
}